// round 17
// baseline (speedup 1.0000x reference)
#include <cuda_runtime.h>

// Problem constants (fixed by the dataset)
#define T_LEN 4096
#define B_SZ  32
#define C_SZ  300
#define W_SZ  128
#define C4    (C_SZ / 4)     // 75 float4 per (t,b) row
#define ROW4  (B_SZ * C4)    // 2400 float4 per t-slice
#define NTHR  480            // 2400 = 480 * 5 exactly
#define UNROLL 5

// FINAL kernel — measured optimum, reproduced 5x at 51.68-51.71us total
// (46.5-46.8us kernel, DRAM ~70%, 5.6 TB/s, regs=32, occ ~78%).
//
// One block per t. Warps 0-7 compute the 32 per-sample segment positions:
// warp-scan of the 128 durations (int4/lane + shfl prefix) gives segment
// starts; a ballot over "lane's first start <= t" + clz picks the owning
// lane; an in-lane select refines to the exact start. Then a 3-phase
// stream: batched __ldcs x-loads (MLP=5), branched __ldcg pe gather + add
// (pe is a 6MB L2-resident table with zero intra-block reuse — L1 caching
// it is pure pollution), batched __stcs stores (eager in-kernel drain;
// default write-back defers ~150MB of dirty L2 into the next graph replay).
//
// Why this is the roofline (15 profiles of evidence): DRAM% pinned at
// 66-72% across occupancies 40-83% and every scheduling scheme = the HBM
// controller's read/write-turnaround ceiling for a 50/50 mixed stream.
// Falsified alternatives (total us): reg-hoisted loads 52.3 (occ collapse),
// T_PER=2@480thr 53.7 (regs 44), cp.async staging 53.8, branchless pe 55.4,
// merged add+store 53.3, persistent blocks 63.5 (barrier lockstep),
// default-policy ld/st 53.3/53.0, 2-slice@960thr 51.68 (tie, worse kernel).
__global__ void __launch_bounds__(NTHR) k_fused(const float4* __restrict__ x,
                                                const float4* __restrict__ pe,
                                                const int*    __restrict__ dur,
                                                float4*       __restrict__ out) {
    __shared__ int s_pos[B_SZ];
    const int t    = blockIdx.x;
    const int warp = threadIdx.x >> 5;
    const int lane = threadIdx.x & 31;
    const int tid  = threadIdx.x;

    // ---- prologue: segment position for 4 samples per warp (warps 0-7) ----
    if (warp < 8) {
#pragma unroll
        for (int k = 0; k < 4; k++) {
            const int b = warp * 4 + k;
            int4 d4 = __ldg((const int4*)(dur + b * W_SZ + lane * 4));
            int s = d4.x + d4.y + d4.z + d4.w;
            int incl = s;
#pragma unroll
            for (int o = 1; o < 32; o <<= 1) {
                int vv = __shfl_up_sync(0xffffffffu, incl, o);
                if (lane >= o) incl += vv;
            }
            int base = incl - s;                   // exclusive prefix across lanes
            int st0 = base;
            int st1 = base + d4.x;
            int st2 = st1 + d4.y;
            int st3 = st2 + d4.z;
            int tot = __shfl_sync(0xffffffffu, incl, 31);

            // Largest start <= t: starts nondecreasing across lanes.
            unsigned m = __ballot_sync(0xffffffffu, st0 <= t);
            int L = 31 - __clz(m);
            int loc = st0;
            if (st1 <= t) loc = st1;
            if (st2 <= t) loc = st2;
            if (st3 <= t) loc = st3;
            int seg = __shfl_sync(0xffffffffu, loc, L);

            if (lane == 0) s_pos[b] = (t < tot) ? (t - seg) : -1;
        }
    }
    __syncthreads();

    // ---- streaming add: exact unroll, batched x loads for MLP ----
    const float4* xrow = x + (size_t)t * ROW4;
    float4*       orow = out + (size_t)t * ROW4;

    float4 v[UNROLL];
    int    bb[UNROLL], cc[UNROLL];
#pragma unroll
    for (int i = 0; i < UNROLL; i++) {
        int j = tid + i * NTHR;
        bb[i] = j / C4;                    // constant divide -> mul/shift
        cc[i] = j - bb[i] * C4;
        v[i]  = __ldcs(xrow + j);          // streaming read (evict-first)
    }
#pragma unroll
    for (int i = 0; i < UNROLL; i++) {
        int p = s_pos[bb[i]];
        if (p >= 0) {
            float4 pv = __ldcg(pe + p * C4 + cc[i]);  // L2-only: no L1 pollution
            v[i].x += pv.x; v[i].y += pv.y; v[i].z += pv.z; v[i].w += pv.w;
        }
    }
#pragma unroll
    for (int i = 0; i < UNROLL; i++) {
        __stcs(orow + tid + i * NTHR, v[i]);          // streaming write
    }
}

extern "C" void kernel_launch(void* const* d_in, const int* in_sizes, int n_in,
                              void* d_out, int out_size) {
    const float* x  = (const float*)d_in[0];
    const float* pe = (const float*)d_in[1];
    const int*   du = (const int*)d_in[2];
    // d_in[3] = train flag, unused by the reference math.
    k_fused<<<T_LEN, NTHR>>>((const float4*)x, (const float4*)pe, du, (float4*)d_out);
}